// round 15
// baseline (speedup 1.0000x reference)
#include <cuda_runtime.h>
#include <cstdint>

// ConditionalSplineSQ2D: out[b] = sum_{g,h,c} param[b,g,h,ii]*param[b,g,h,jj]*coef[g,h,c]
// B=4096, G*G=961 cells, P=8, C=36. Pure HBM stream: 126MB read once.
//
// NEW decomposition (kills the 36-coef register tax that capped MLP for 15
// rounds): warp = 4 b's x 8 cells. Lane (bsub,csub) accumulates PRIVATELY for
// b=b0+bsub over cells csub, csub+8,... Coefs come from smem per cell
// (chunk-local, padded 52 words/cell: LDS.128 conflict-free, 4-way bsub
// broadcast) -> zero persistent coef regs -> 4-deep register param pipeline
// (4KB/warp in flight, 32 warps/SM via 4x256-thread CTAs). No in-loop
// reduction at all; epilogue = 3 shfl + 1 store per warp into per-chunk
// scratch; tiny finisher kernel sums the 4 chunk partials per b.

#define GG    961
#define CC    36
#define CP    52                      // padded words per cell (bank-friendly)
#define MAXC  241                     // max cells per chunk
#define NBMAX 4096
#define SMEM_DYN (MAXC * CP * 4)      // 50128 B

__device__ float g_scratch[4 * NBMAX];

// Quadratic form for one cell: coef rows padded at word offsets
// {0,8,16,24,32,36,40,44}, row r holds cf(r,j) j=r..7.
__device__ __forceinline__ float cellq(const float* __restrict__ cw,
                                       const float pv[8])
{
    float4 c0 = *(const float4*)(cw + 0);
    float4 c1 = *(const float4*)(cw + 4);
    float4 c2 = *(const float4*)(cw + 8);
    float4 c3 = *(const float4*)(cw + 12);
    float4 c4 = *(const float4*)(cw + 16);
    float4 c5 = *(const float4*)(cw + 20);
    float4 c6 = *(const float4*)(cw + 24);
    float4 c7 = *(const float4*)(cw + 28);
    float4 c8 = *(const float4*)(cw + 32);
    float4 c9 = *(const float4*)(cw + 36);
    float4 ca = *(const float4*)(cw + 40);
    float4 cb = *(const float4*)(cw + 44);

    float r = 0.0f;
    float q;
    q = c0.x * pv[0];
    q = fmaf(c0.y, pv[1], q); q = fmaf(c0.z, pv[2], q); q = fmaf(c0.w, pv[3], q);
    q = fmaf(c1.x, pv[4], q); q = fmaf(c1.y, pv[5], q); q = fmaf(c1.z, pv[6], q);
    q = fmaf(c1.w, pv[7], q);
    r = fmaf(pv[0], q, r);

    q = c2.x * pv[1];
    q = fmaf(c2.y, pv[2], q); q = fmaf(c2.z, pv[3], q); q = fmaf(c2.w, pv[4], q);
    q = fmaf(c3.x, pv[5], q); q = fmaf(c3.y, pv[6], q); q = fmaf(c3.z, pv[7], q);
    r = fmaf(pv[1], q, r);

    q = c4.x * pv[2];
    q = fmaf(c4.y, pv[3], q); q = fmaf(c4.z, pv[4], q); q = fmaf(c4.w, pv[5], q);
    q = fmaf(c5.x, pv[6], q); q = fmaf(c5.y, pv[7], q);
    r = fmaf(pv[2], q, r);

    q = c6.x * pv[3];
    q = fmaf(c6.y, pv[4], q); q = fmaf(c6.z, pv[5], q); q = fmaf(c6.w, pv[6], q);
    q = fmaf(c7.x, pv[7], q);
    r = fmaf(pv[3], q, r);

    q = c8.x * pv[4];
    q = fmaf(c8.y, pv[5], q); q = fmaf(c8.z, pv[6], q); q = fmaf(c8.w, pv[7], q);
    r = fmaf(pv[4], q, r);

    q = c9.x * pv[5];
    q = fmaf(c9.y, pv[6], q); q = fmaf(c9.z, pv[7], q);
    r = fmaf(pv[5], q, r);

    q = ca.x * pv[6];
    q = fmaf(ca.y, pv[7], q);
    r = fmaf(pv[6], q, r);

    q = cb.x * pv[7];
    r = fmaf(pv[7], q, r);
    return r;
}

__global__ __launch_bounds__(256, 4)
void sq2d_main(const float* __restrict__ param,
               const float* __restrict__ coef,
               int nB)
{
    extern __shared__ float cfs[];

    const int tid   = threadIdx.x;
    const int chunk = blockIdx.x & 3;
    const int gbase = (blockIdx.x >> 2) * 8;          // 8 bgroups per CTA
    const int lo    = (GG * chunk) >> 2;              // 0,240,480,720
    const int hi    = (GG * (chunk + 1)) >> 2;        // 240,480,720,961
    const int ncell = hi - lo;                        // 240 or 241

    // Stage this chunk's coefs into padded smem (zero pads first).
    for (int i = tid; i < ncell * CP; i += 256) cfs[i] = 0.0f;
    __syncthreads();
    for (int idx = tid; idx < ncell * CC; idx += 256) {
        int lc = idx / CC;
        int c  = idx - lc * CC;
        int po;
        if      (c < 8)  po = c;
        else if (c < 15) po = 8  + (c - 8);
        else if (c < 21) po = 16 + (c - 15);
        else if (c < 26) po = 24 + (c - 21);
        else if (c < 30) po = 32 + (c - 26);
        else if (c < 33) po = 36 + (c - 30);
        else if (c < 35) po = 40 + (c - 33);
        else             po = 44;
        cfs[lc * CP + po] = coef[(lo + lc) * CC + c];
    }
    __syncthreads();

    const int lane = tid & 31;
    const int warp = tid >> 5;
    const int bsub = lane >> 3;
    const int csub = lane & 7;
    const int b    = (gbase + warp) * 4 + bsub;

    // Lane reads cells lo+csub+8k for its private b. Per bsub-group the 8
    // lanes cover 256B contiguous -> clean coalescing.
    const float4* pbase = reinterpret_cast<const float4*>(param)
                        + ((size_t)b * GG + lo + csub) * 2;
    const float* cbase = cfs + csub * CP;

    // 4-deep register pipeline over the 30-iteration cell loop.
    float4 A[4][2];
#pragma unroll
    for (int s = 0; s < 4; s++) {
        A[s][0] = __ldg(pbase + s * 16);
        A[s][1] = __ldg(pbase + s * 16 + 1);
    }

    float acc = 0.0f;

#pragma unroll
    for (int k = 0; k < 30; k++) {
        float pv[8] = { A[k & 3][0].x, A[k & 3][0].y, A[k & 3][0].z, A[k & 3][0].w,
                        A[k & 3][1].x, A[k & 3][1].y, A[k & 3][1].z, A[k & 3][1].w };
        // Refill this slab for k+4 (issues once pv copies retire).
        if (k + 4 < 30) {
            A[k & 3][0] = __ldg(pbase + (k + 4) * 16);
            A[k & 3][1] = __ldg(pbase + (k + 4) * 16 + 1);
        }
        acc += cellq(cbase + k * (8 * CP), pv);
    }

    // Tail: chunk 3 has 241 cells -> lanes with csub==0 do one extra cell.
    if (240 + csub < ncell) {
        float4 t0 = __ldg(pbase + 30 * 16);
        float4 t1 = __ldg(pbase + 30 * 16 + 1);
        float pv[8] = { t0.x, t0.y, t0.z, t0.w, t1.x, t1.y, t1.z, t1.w };
        acc += cellq(cbase + 30 * (8 * CP), pv);
    }

    // 8-lane (csub) reduce; lane csub==0 writes the chunk partial for its b.
    acc += __shfl_xor_sync(0xffffffffu, acc, 1);
    acc += __shfl_xor_sync(0xffffffffu, acc, 2);
    acc += __shfl_xor_sync(0xffffffffu, acc, 4);
    if (csub == 0 && b < NBMAX)
        g_scratch[chunk * NBMAX + b] = acc;
}

__global__ void sq2d_fin(float* __restrict__ out, int nB)
{
    int b = blockIdx.x * blockDim.x + threadIdx.x;
    if (b < nB)
        out[b] = g_scratch[b] + g_scratch[NBMAX + b]
               + g_scratch[2 * NBMAX + b] + g_scratch[3 * NBMAX + b];
}

extern "C" void kernel_launch(void* const* d_in, const int* in_sizes, int n_in,
                              void* d_out, int out_size)
{
    const float* param = (const float*)d_in[0];   // [B, 31, 31, 8] f32
    const float* coef  = (const float*)d_in[1];   // [31, 31, 36]   f32
    float* out = (float*)d_out;                    // [B] f32

    const int nB = in_sizes[0] / (GG * 8);

    static int configured = -1;
    if (configured < 0) {
        cudaFuncSetAttribute(sq2d_main,
                             cudaFuncAttributeMaxDynamicSharedMemorySize, SMEM_DYN);
        configured = 1;
    }

    const int grid = (nB / 32) * 4;    // (bgroups/8 per CTA) x 4 chunks = 512
    sq2d_main<<<grid, 256, SMEM_DYN>>>(param, coef, nB);
    sq2d_fin<<<(nB + 255) / 256, 256>>>(out, nB);
}

// round 16
// speedup vs baseline: 1.9904x; 1.9904x over previous
#include <cuda_runtime.h>
#include <cstdint>

// ConditionalSplineSQ2D: out[b] = sum_{g,h,c} param[b,g,h,ii]*param[b,g,h,jj]*coef[g,h,c]
// B=4096, G*G=961 cells, P=8, C=36. Pure HBM stream: 126MB read once.
//
// SM-specialization: the register file can't hold 961x36 coefs AND a deep
// load pipeline (the 16-round 4.4TB/s wall). Split cells across 2 CTAs per
// b-stream: chunk0 = cells 0..479, chunk1 = 480..960. Each thread holds 18
// coefs (warp-pair covers 32 cells; even warp: coef rows {0,1,(2,2..4)},
// odd warp: rows {(2,5..7),3..7}; both load the same 32B rows - dedup'd in
// L1/L2, zero extra DRAM). Freed regs fund a 4-deep slab pipeline (4x32B
// per thread in flight). Epilogue: raw STS partials, one barrier, warp w
// reduces b_w, one atomicAdd per (CTA,b) combines the chunks (out pre-zeroed).

#define GG    961
#define CC    36
#define NTHR  1024
#define MAXK  28
#define SMEM_DYN (MAXK * NTHR * 4)   // 114688 B

extern __shared__ float part[];      // [MAXK][NTHR]

// Half-quadratic for one cell. a = p0..p3, b = p4..p7.
// HALF 0: rows (0,0..7),(1,1..7),(2,2..4)   -> cf[0..17] = c0..c17
// HALF 1: rows (2,5..7),(3,3..7),(4,..),(5,..),(6,..),(7,7) -> cf[0..17] = c18..c35
template <int HALF>
__device__ __forceinline__ float cellpart(const float* __restrict__ cf,
                                          const float4 a, const float4 b)
{
    float acc, q;
    if (HALF == 0) {
        q = cf[0]*a.x; q=fmaf(cf[1],a.y,q); q=fmaf(cf[2],a.z,q); q=fmaf(cf[3],a.w,q);
        q=fmaf(cf[4],b.x,q); q=fmaf(cf[5],b.y,q); q=fmaf(cf[6],b.z,q); q=fmaf(cf[7],b.w,q);
        acc = a.x*q;
        q = cf[8]*a.y; q=fmaf(cf[9],a.z,q); q=fmaf(cf[10],a.w,q);
        q=fmaf(cf[11],b.x,q); q=fmaf(cf[12],b.y,q); q=fmaf(cf[13],b.z,q); q=fmaf(cf[14],b.w,q);
        acc = fmaf(a.y,q,acc);
        q = cf[15]*a.z; q=fmaf(cf[16],a.w,q); q=fmaf(cf[17],b.x,q);
        acc = fmaf(a.z,q,acc);
    } else {
        q = cf[0]*b.y; q=fmaf(cf[1],b.z,q); q=fmaf(cf[2],b.w,q);
        acc = a.z*q;
        q = cf[3]*a.w; q=fmaf(cf[4],b.x,q); q=fmaf(cf[5],b.y,q);
        q=fmaf(cf[6],b.z,q); q=fmaf(cf[7],b.w,q);
        acc = fmaf(a.w,q,acc);
        q = cf[8]*b.x; q=fmaf(cf[9],b.y,q); q=fmaf(cf[10],b.z,q); q=fmaf(cf[11],b.w,q);
        acc = fmaf(b.x,q,acc);
        q = cf[12]*b.y; q=fmaf(cf[13],b.z,q); q=fmaf(cf[14],b.w,q);
        acc = fmaf(b.y,q,acc);
        q = cf[15]*b.z; q=fmaf(cf[16],b.w,q);
        acc = fmaf(b.z,q,acc);
        acc = fmaf(b.w, cf[17]*b.w, acc);
    }
    return acc;
}

template <int HALF>
__device__ __forceinline__ void runloop(const char* gptr0, uint32_t bstep,
                                        int K, const float* __restrict__ cf,
                                        float* prow)
{
    float4 A0,A1,B0,B1,C0,C1,D0,D1;
    const char* p = gptr0;
    // Prefill 4 slabs (K >= 4 in practice; guarded anyway).
    {
        A0 = __ldg((const float4*)p); A1 = __ldg((const float4*)p + 1); p += bstep;
        if (K > 1) { B0 = __ldg((const float4*)p); B1 = __ldg((const float4*)p + 1); }
        p += bstep;
        if (K > 2) { C0 = __ldg((const float4*)p); C1 = __ldg((const float4*)p + 1); }
        p += bstep;
        if (K > 3) { D0 = __ldg((const float4*)p); D1 = __ldg((const float4*)p + 1); }
        p += bstep;
    }

#pragma unroll 1
    for (int j = 0; j < K; j += 4) {
        prow[0] = cellpart<HALF>(cf, A0, A1);
        if (j + 4 < K) { A0 = __ldg((const float4*)p); A1 = __ldg((const float4*)p + 1); }
        p += bstep;
        if (j + 1 < K) {
            prow[NTHR] = cellpart<HALF>(cf, B0, B1);
            if (j + 5 < K) { B0 = __ldg((const float4*)p); B1 = __ldg((const float4*)p + 1); }
        }
        p += bstep;
        if (j + 2 < K) {
            prow[2 * NTHR] = cellpart<HALF>(cf, C0, C1);
            if (j + 6 < K) { C0 = __ldg((const float4*)p); C1 = __ldg((const float4*)p + 1); }
        }
        p += bstep;
        if (j + 3 < K) {
            prow[3 * NTHR] = cellpart<HALF>(cf, D0, D1);
            if (j + 7 < K) { D0 = __ldg((const float4*)p); D1 = __ldg((const float4*)p + 1); }
        }
        p += bstep;
        prow += 4 * NTHR;
    }
}

template <int CSTRIDE>
__global__ __launch_bounds__(NTHR, 1)
void sq2d_main(const float* __restrict__ param,
               const float* __restrict__ coef,
               float* __restrict__ out,
               int nB, int rstride)
{
    const int stride = (CSTRIDE > 0) ? CSTRIDE : rstride;
    const int tid  = threadIdx.x;
    const int lane = tid & 31;
    const int warp = tid >> 5;
    const int chunk = blockIdx.x & 1;
    const int g     = blockIdx.x >> 1;          // b-stream id, 0..stride-1

    const int lo      = chunk ? 480 : 0;
    const int ncell   = chunk ? 481 : 480;
    const int halfsel = warp & 1;                // warp-uniform coef half
    const int cellloc = (warp >> 1) * 32 + lane; // warp-pair covers 32 cells
    const bool active = (cellloc < ncell);
    const int cell = lo + (active ? cellloc : ncell - 1);   // clamp addresses

    // 18 coefficients in registers (0 for inactive -> partial contributes 0).
    float cf[18];
#pragma unroll
    for (int i = 0; i < 18; i++)
        cf[i] = active ? coef[cell * CC + halfsel * 18 + i] : 0.0f;

    const int K = (nB - g + stride - 1) / stride;
    const char* gptr0 = (const char*)param + (size_t)cell * 32
                      + (size_t)g * (size_t)(GG * 32);
    const uint32_t bstep = (uint32_t)(GG * 32) * (uint32_t)stride;

    if (halfsel == 0) runloop<0>(gptr0, bstep, K, cf, &part[tid]);
    else              runloop<1>(gptr0, bstep, K, cf, &part[tid]);

    __syncthreads();   // the only block barrier

    // Warp w finalizes b = g + w*stride; atomicAdd combines the two chunks.
    if (warp < K) {
        const float* row = &part[warp * NTHR];
        float v = 0.0f;
#pragma unroll
        for (int q = 0; q < 32; q++)
            v += row[q * 32 + lane];
#pragma unroll
        for (int o = 16; o > 0; o >>= 1)
            v += __shfl_xor_sync(0xffffffffu, v, o);
        if (lane == 0)
            atomicAdd(&out[g + warp * stride], v);
    }
}

__global__ void sq2d_zero(float* __restrict__ out, int n)
{
    int i = blockIdx.x * blockDim.x + threadIdx.x;
    if (i < n) out[i] = 0.0f;
}

extern "C" void kernel_launch(void* const* d_in, const int* in_sizes, int n_in,
                              void* d_out, int out_size)
{
    const float* param = (const float*)d_in[0];   // [B, 31, 31, 8] f32
    const float* coef  = (const float*)d_in[1];   // [31, 31, 36]   f32
    float* out = (float*)d_out;                    // [B] f32

    const int nB = in_sizes[0] / (GG * 8);

    static int configured = -1;
    if (configured < 0) {
        cudaFuncSetAttribute(sq2d_main<152>,
                             cudaFuncAttributeMaxDynamicSharedMemorySize, SMEM_DYN);
        cudaFuncSetAttribute(sq2d_main<0>,
                             cudaFuncAttributeMaxDynamicSharedMemorySize, SMEM_DYN);
        configured = 1;
    }

    int dev = 0, sms = 0;
    cudaGetDevice(&dev);
    cudaDeviceGetAttribute(&sms, cudaDevAttrMultiProcessorCount, dev);
    if (sms <= 0) sms = 152;

    int stride = sms;
    const int min_stride = (nB + MAXK - 1) / MAXK;   // keep K <= MAXK
    if (stride < min_stride) stride = min_stride;
    if (stride > nB) stride = nB;

    sq2d_zero<<<(out_size + 255) / 256, 256>>>(out, out_size);

    const int grid = 2 * stride;
    if (stride == 152)
        sq2d_main<152><<<grid, NTHR, SMEM_DYN>>>(param, coef, out, nB, stride);
    else
        sq2d_main<0><<<grid, NTHR, SMEM_DYN>>>(param, coef, out, nB, stride);
}